// round 13
// baseline (speedup 1.0000x reference)
#include <cuda_runtime.h>
#include <cuda_bf16.h>
#include <math.h>
#include <cstdint>

// Shapes (fixed per reference): B=512, T=256, F=D=1024
#define BB 512
#define TT 256
#define FF 1024

// ---------------- scratch (__device__ globals; no allocs allowed) -----------
// Split matrices stored TILED: block (rb, s) = rows [rb*64,+64) x k [s*64,+64)
//   -> 16 KB: [hi tile 8KB][lo tile 8KB], each tile 64 rows x 128B, XOR-swizzled.
__device__ __align__(16) __nv_bfloat16 g_xa[BB * 2048];   // split(z), then split(c)
__device__ __align__(16) __nv_bfloat16 g_xb[BB * 2048];   // split(q) (GEMM1 epi)
__device__ __align__(16) __nv_bfloat16 g_wq2[FF * 2048];  // split(Wq)
__device__ __align__(16) __nv_bfloat16 g_wk2[FF * 2048];  // splitT(Wk)
__device__ __align__(16) __nv_bfloat16 g_wv2[FF * 2048];  // split(Wv)
__device__ float g_u[BB * FF];

// ---------------- ptx helpers ----------------------------------------------
__device__ __forceinline__ uint32_t smem_u32(const void* p) {
    uint32_t a;
    asm("{ .reg .u64 t; cvta.to.shared.u64 t, %1; cvt.u32.u64 %0, t; }"
        : "=r"(a) : "l"(p));
    return a;
}
__device__ __forceinline__ void ldsm_x4(uint32_t (&r)[4], uint32_t addr) {
    asm volatile("ldmatrix.sync.aligned.m8n8.x4.shared.b16 {%0,%1,%2,%3}, [%4];"
                 : "=r"(r[0]), "=r"(r[1]), "=r"(r[2]), "=r"(r[3]) : "r"(addr));
}
__device__ __forceinline__ void mma_bf16(float (&d)[4], const uint32_t (&a)[4],
                                         uint32_t b0, uint32_t b1) {
    asm volatile(
        "mma.sync.aligned.m16n8k16.row.col.f32.bf16.bf16.f32 "
        "{%0,%1,%2,%3}, {%4,%5,%6,%7}, {%8,%9}, {%0,%1,%2,%3};"
        : "+f"(d[0]), "+f"(d[1]), "+f"(d[2]), "+f"(d[3])
        : "r"(a[0]), "r"(a[1]), "r"(a[2]), "r"(a[3]), "r"(b0), "r"(b1));
}

#define MBAR_INIT(a, c) asm volatile("mbarrier.init.shared.b64 [%0], %1;" :: "r"(a), "r"(c) : "memory")
#define MBAR_EXPECT(a, tx) asm volatile("mbarrier.arrive.expect_tx.shared.b64 _, [%0], %1;" :: "r"(a), "r"(tx) : "memory")
#define FENCE_ASYNC() asm volatile("fence.proxy.async.shared::cta;" ::: "memory")

__device__ __forceinline__ void bulk_g2s(uint32_t dst, const void* src,
                                         uint32_t bytes, uint32_t mbar) {
    asm volatile(
        "cp.async.bulk.shared::cluster.global.mbarrier::complete_tx::bytes "
        "[%0], [%1], %2, [%3];"
        :: "r"(dst), "l"(src), "r"(bytes), "r"(mbar) : "memory");
}

#define MBAR_WAIT(a, ph) do {                                                    \
    uint32_t _m = (a), _p = (ph), _d;                                            \
    asm volatile("{\n\t.reg .pred p;\n\t"                                        \
        "mbarrier.try_wait.parity.acquire.cta.shared::cta.b64 p, [%1], %2;\n\t"  \
        "selp.b32 %0, 1, 0, p;\n\t}" : "=r"(_d) : "r"(_m), "r"(_p) : "memory");  \
    if (!_d) {                                                                   \
        asm volatile("{\n\t.reg .pred P1;\n\t"                                   \
            "W%=:\n\t"                                                           \
            "mbarrier.try_wait.parity.acquire.cta.shared::cta.b64 P1, [%0], %1, 0x989680;\n\t" \
            "@P1 bra.uni D%=;\n\t"                                               \
            "bra.uni W%=;\n\t"                                                   \
            "D%=:\n\t}" :: "r"(_m), "r"(_p) : "memory");                         \
    }                                                                            \
} while (0)

// ---------------- fp32 -> bf16 hi/lo split + tiled addressing ----------------
__device__ __forceinline__ void split1(float x, __nv_bfloat16& h, __nv_bfloat16& l) {
    h = __float2bfloat16(x);
    l = __float2bfloat16(x - __bfloat162float(h));
}
__device__ __forceinline__ uint32_t pack_bf(__nv_bfloat16 a, __nv_bfloat16 b) {
    return (uint32_t)__bfloat16_as_ushort(a) | ((uint32_t)__bfloat16_as_ushort(b) << 16);
}
// byte offset of (row, kcol, part) in a tiled split array
__device__ __forceinline__ size_t tiled_off(int row, int kcol, int part) {
    int tb = (row >> 6) * 16 + (kcol >> 6);
    int r = row & 63, c = kcol & 63;
    return (size_t)tb * 16384 + (size_t)part * 8192
         + (size_t)(r * 128 + ((((c >> 3) ^ (r & 7))) << 4) + (c & 7) * 2);
}

// ---------------------------------------------------------------------------
// ONE merged prep kernel (single launch, full chip):
//   blocks [0,512)        : split(z)        -> g_xa
//   blocks [512,1536)     : split(Wq)       -> g_wq2
//   blocks [1536,2560)    : split(Wv)       -> g_wv2
//   blocks [2560,3584)    : splitT(Wk)      -> g_wk2   (row=n, kcol=k)
// ---------------------------------------------------------------------------
__device__ __forceinline__ void split_rowmajor_block(
    const float4* __restrict__ in, char* __restrict__ out, int blk, int tid)
{
    int i = blk * 256 + tid;
    float4 v = in[i];
    int r = i >> 8, c4 = (i & 255) * 4;
    __nv_bfloat16 h0, h1, h2, h3, l0, l1, l2, l3;
    split1(v.x, h0, l0); split1(v.y, h1, l1);
    split1(v.z, h2, l2); split1(v.w, h3, l3);
    uint2 hv, lv;
    hv.x = pack_bf(h0, h1); hv.y = pack_bf(h2, h3);
    lv.x = pack_bf(l0, l1); lv.y = pack_bf(l2, l3);
    *reinterpret_cast<uint2*>(out + tiled_off(r, c4, 0)) = hv;
    *reinterpret_cast<uint2*>(out + tiled_off(r, c4, 1)) = lv;
}

__global__ __launch_bounds__(256)
void split_all(const float4* __restrict__ z, const float4* __restrict__ Wq,
               const float4* __restrict__ Wv, const float* __restrict__ Wk,
               char* __restrict__ xa, char* __restrict__ wq2,
               char* __restrict__ wv2, char* __restrict__ wk2)
{
    const int bid = blockIdx.x;
    const int tid = threadIdx.x;
    if (bid < 512) {
        split_rowmajor_block(z, xa, bid, tid);
    } else if (bid < 1536) {
        split_rowmajor_block(Wq, wq2, bid - 512, tid);
    } else if (bid < 2560) {
        split_rowmajor_block(Wv, wv2, bid - 1536, tid);
    } else {
        // transpose-split of Wk [K][N] -> tiled rows = n, kcols = k
        __shared__ float t[32][33];
        const int b2 = bid - 2560;
        const int k0 = (b2 & 31) * 32, n0 = (b2 >> 5) * 32;
        const int tx = tid & 31, ty = tid >> 5;   // ty 0..7
#pragma unroll
        for (int i = 0; i < 4; i++)
            t[ty * 4 + i][tx] = ((const float*)Wk)[(size_t)(k0 + ty * 4 + i) * FF + n0 + tx];
        __syncthreads();
        __nv_bfloat16 h[4], l[4];
#pragma unroll
        for (int i = 0; i < 4; i++) split1(t[tx][ty * 4 + i] * 0.f + t[ty * 0 + tx][ty * 4 + i], h[i], l[i]);
        // NOTE: the expression above must be exactly t[tx][ty*4+i]; keep simple:
#pragma unroll
        for (int i = 0; i < 4; i++) split1(t[tx][ty * 4 + i], h[i], l[i]);
        uint2 hv, lv;
        hv.x = pack_bf(h[0], h[1]); hv.y = pack_bf(h[2], h[3]);
        lv.x = pack_bf(l[0], l[1]); lv.y = pack_bf(l[2], l[3]);
        // wait: thread holds n = n0+tx?? recompute cleanly below
        int n = n0 + tx, kk = k0 + ty * 4;
        // t[a][b] = Wk[k0+a][n0+b]; we need Wk[kk + j][n] = t[ty*4+j][tx]
#pragma unroll
        for (int i = 0; i < 4; i++) split1(t[ty * 4 + i][tx], h[i], l[i]);
        hv.x = pack_bf(h[0], h[1]); hv.y = pack_bf(h[2], h[3]);
        lv.x = pack_bf(l[0], l[1]); lv.y = pack_bf(l[2], l[3]);
        *reinterpret_cast<uint2*>(wk2 + tiled_off(n, kk, 0)) = hv;
        *reinterpret_cast<uint2*>(wk2 + tiled_off(n, kk, 1)) = lv;
    }
}

// ---------------------------------------------------------------------------
// HMMA bf16 NT GEMM on tiled split operands, bulk-copy pipeline.
//   D[512][1024] = (Ahi+Alo) @ (Bhi+Blo)^T  (3 passes, drops lo*lo).
// CTA tile 64x64, grid (16,8)=128 CTAs, 8 warps (2M x 4N), warp tile 32x16.
// 16 stages of BK=64; 3-slot smem ring, 32KB/slot ([Ahi|Alo|Bhi|Blo] 8KB each),
// filled by 2 cp.async.bulk per stage.
// OUTMODE 0: fp32 [512][1024] (+bias).  1: tiled split array (+bias).
// ---------------------------------------------------------------------------
#define STG_B 32768
#define SMEM_GEMM (1024 + 3 * STG_B)   // 99328

__device__ __forceinline__ void issue_stage(uint32_t mbar, uint32_t dst,
                                            const char* Atl, const char* Btl,
                                            int mb, int nb, int s)
{
    MBAR_EXPECT(mbar, 32768u);
    bulk_g2s(dst,          Atl + (size_t)(mb * 16 + s) * 16384, 16384u, mbar);
    bulk_g2s(dst + 16384u, Btl + (size_t)(nb * 16 + s) * 16384, 16384u, mbar);
}

template <bool HASBIAS, int OUTMODE>
__global__ __launch_bounds__(256)
void mma_gemm(const char* __restrict__ Atl, const char* __restrict__ Btl,
              const float* __restrict__ bias, void* __restrict__ Out)
{
    extern __shared__ char smem[];
    const uint32_t sb = smem_u32(smem);
    const int tid  = threadIdx.x;
    const int wid  = tid >> 5;
    const int lane = tid & 31;
    const int wm = wid >> 2;       // 2 M groups of 32 rows
    const int wn = wid & 3;        // 4 N groups of 16 cols
    const int nb = blockIdx.x;
    const int mb = blockIdx.y;

    const uint32_t tiles = sb + 1024;

    if (tid == 0) {
#pragma unroll
        for (int j = 0; j < 3; j++) MBAR_INIT(sb + 8 * j, 1);
        FENCE_ASYNC();
    }
    __syncthreads();
    if (tid == 0) {
#pragma unroll
        for (int p = 0; p < 3; p++)
            issue_stage(sb + 8 * p, tiles + p * STG_B, Atl, Btl, mb, nb, p);
    }

    // ldmatrix per-thread geometry
    const int q  = lane >> 3;
    const int lr = lane & 7;
    const int rowA0 = wm * 32 + (q & 1) * 8 + lr;        // mf adds 16
    const int rowB  = wn * 16 + (q >> 1) * 8 + lr;
    const uint32_t arow0 = rowA0 * 128, arow1 = (rowA0 + 16) * 128;
    const uint32_t brow  = rowB * 128;
    const int a0m = rowA0 & 7, a1m = (rowA0 + 16) & 7, bm = rowB & 7;
    const int qk = q >> 1, qb = q & 1;

    float acc[2][2][4];
#pragma unroll
    for (int i = 0; i < 2; i++)
#pragma unroll
        for (int j = 0; j < 2; j++)
#pragma unroll
            for (int e = 0; e < 4; e++) acc[i][j][e] = 0.f;

    for (int s = 0; s < 16; s++) {
        const int slot = s % 3;
        MBAR_WAIT(sb + 8 * slot, (s / 3) & 1);
        const uint32_t stg = tiles + slot * STG_B;

#pragma unroll
        for (int pass = 0; pass < 3; pass++) {
            const uint32_t ab = stg + ((pass == 1) ? 8192u : 0u);
            const uint32_t bb = stg + 16384u + ((pass == 2) ? 8192u : 0u);
#pragma unroll
            for (int kk = 0; kk < 4; kk++) {
                uint32_t a0[4], a1[4], b0[4];
                ldsm_x4(a0, ab + arow0 + (uint32_t)(((2 * kk + qk) ^ a0m) << 4));
                ldsm_x4(a1, ab + arow1 + (uint32_t)(((2 * kk + qk) ^ a1m) << 4));
                ldsm_x4(b0, bb + brow  + (uint32_t)(((2 * kk + qb) ^ bm)  << 4));
                mma_bf16(acc[0][0], a0, b0[0], b0[1]);
                mma_bf16(acc[0][1], a0, b0[2], b0[3]);
                mma_bf16(acc[1][0], a1, b0[0], b0[1]);
                mma_bf16(acc[1][1], a1, b0[2], b0[3]);
            }
        }
        __syncthreads();   // all warps done reading this slot
        if (tid == 0 && s + 3 < 16)
            issue_stage(sb + 8 * slot, stg, Atl, Btl, mb, nb, s + 3);
    }

    // epilogue
    const int r0 = mb * 64 + wm * 32 + (lane >> 2);
    const int cb = nb * 64 + wn * 16 + 2 * (lane & 3);
#pragma unroll
    for (int mf = 0; mf < 2; mf++) {
        const int rowA = r0 + mf * 16;
        const int rowB2 = rowA + 8;
#pragma unroll
        for (int nf = 0; nf < 2; nf++) {
            const int col = cb + nf * 8;
            float bx = 0.f, by = 0.f;
            if (HASBIAS) { bx = bias[col]; by = bias[col + 1]; }
            float d0 = acc[mf][nf][0] + bx, d1 = acc[mf][nf][1] + by;
            float d2 = acc[mf][nf][2] + bx, d3 = acc[mf][nf][3] + by;
            if (OUTMODE == 1) {
                char* o2 = (char*)Out;
                __nv_bfloat16 h0, h1, h2, h3, l0, l1, l2, l3;
                split1(d0, h0, l0); split1(d1, h1, l1);
                split1(d2, h2, l2); split1(d3, h3, l3);
                *reinterpret_cast<uint32_t*>(o2 + tiled_off(rowA, col, 0))  = pack_bf(h0, h1);
                *reinterpret_cast<uint32_t*>(o2 + tiled_off(rowA, col, 1))  = pack_bf(l0, l1);
                *reinterpret_cast<uint32_t*>(o2 + tiled_off(rowB2, col, 0)) = pack_bf(h2, h3);
                *reinterpret_cast<uint32_t*>(o2 + tiled_off(rowB2, col, 1)) = pack_bf(l2, l3);
            } else {
                float* o = (float*)Out;
                *reinterpret_cast<float2*>(o + (size_t)rowA * FF + col)  = make_float2(d0, d1);
                *reinterpret_cast<float2*>(o + (size_t)rowB2 * FF + col) = make_float2(d2, d3);
            }
        }
    }
}

// ---------------------------------------------------------------------------
// Fused single-query attention: one cp.async.bulk (32KB) per 8-row tile,
// 3-slot mbarrier ring, online softmax, single HBM pass over p.
// Epilogue writes c DIRECTLY as tiled bf16 hi/lo split (GEMM3's A operand).
// smem: [0,24) mbars | [64,96) s_sm | [1024,5120) u | [5120,+96K) tiles
// ---------------------------------------------------------------------------
#define ATTN_SMEM (5120 + 3 * 32768)   // 103424

__global__ __launch_bounds__(256)
void attn_kernel(const float* __restrict__ u, const float* __restrict__ p,
                 char* __restrict__ c_split)
{
    extern __shared__ char smem[];
    const uint32_t sb = smem_u32(smem);
    float*  s_sm = (float*)(smem + 64);
    float4* u_s  = (float4*)(smem + 1024);

    const int b    = blockIdx.x;
    const int tid  = threadIdx.x;
    const int lane = tid & 31;
    const int w    = tid >> 5;

    if (tid == 0) {
        MBAR_INIT(sb + 0, 1);
        MBAR_INIT(sb + 8, 1);
        MBAR_INIT(sb + 16, 1);
        FENCE_ASYNC();
    }
    u_s[tid] = reinterpret_cast<const float4*>(u + (size_t)b * FF)[tid];
    __syncthreads();

    const char* pb = (const char*)(p + (size_t)b * TT * FF);
    if (tid == 0) {
#pragma unroll
        for (int j = 0; j < 3; j++) {
            MBAR_EXPECT(sb + 8 * j, 32768u);
            bulk_g2s(sb + 5120 + j * 32768, pb + (size_t)j * 32768, 32768u, sb + 8 * j);
        }
    }

    float4 acc = make_float4(0.f, 0.f, 0.f, 0.f);
    float m = -INFINITY;
    float l = 0.f;

    for (int it = 0; it < TT / 8; it++) {
        const int slot = it % 3;
        MBAR_WAIT(sb + 8 * slot, (it / 3) & 1);
        const float4* tile = (const float4*)(smem + 5120 + slot * 32768);

        // scores: warp w computes dot(u, local row w)
        float partial = 0.f;
#pragma unroll
        for (int k = 0; k < 8; k++) {
            float4 a  = tile[w * 256 + k * 32 + lane];
            float4 uu = u_s[k * 32 + lane];
            partial += a.x * uu.x + a.y * uu.y + a.z * uu.z + a.w * uu.w;
        }
#pragma unroll
        for (int off = 16; off; off >>= 1)
            partial += __shfl_xor_sync(0xffffffffu, partial, off);
        if (lane == 0) s_sm[w] = partial;
        __syncthreads();

        // online softmax (redundant per thread, identical values)
        float s0[8], wv[8];
        float tmax = -INFINITY;
#pragma unroll
        for (int i = 0; i < 8; i++) { s0[i] = s_sm[i]; tmax = fmaxf(tmax, s0[i]); }
        float m_new = fmaxf(m, tmax);
        float cf = __expf(m - m_new);   // it=0: exp(-inf)=0, acc is 0 anyway
        float wsum = 0.f;
#pragma unroll
        for (int i = 0; i < 8; i++) { wv[i] = __expf(s0[i] - m_new); wsum += wv[i]; }
        l = l * cf + wsum;
        m = m_new;
        acc.x *= cf; acc.y *= cf; acc.z *= cf; acc.w *= cf;

#pragma unroll
        for (int i = 0; i < 8; i++) {
            float4 v = tile[i * 256 + tid];
            acc.x += wv[i] * v.x;
            acc.y += wv[i] * v.y;
            acc.z += wv[i] * v.z;
            acc.w += wv[i] * v.w;
        }
        __syncthreads();   // everyone done with this slot (and s_sm)

        if (tid == 0 && it + 3 < TT / 8) {
            MBAR_EXPECT(sb + 8 * slot, 32768u);
            bulk_g2s(sb + 5120 + slot * 32768, pb + (size_t)(it + 3) * 32768,
                     32768u, sb + 8 * slot);
        }
    }

    // epilogue: c[b][tid*4..+3] -> tiled bf16 split (GEMM3 A operand)
    const float inv = 1.f / l;
    const int c4 = tid * 4;
    __nv_bfloat16 h0, h1, h2, h3, l0, l1, l2, l3;
    split1(acc.x * inv, h0, l0); split1(acc.y * inv, h1, l1);
    split1(acc.z * inv, h2, l2); split1(acc.w * inv, h3, l3);
    uint2 hv, lv;
    hv.x = pack_bf(h0, h1); hv.y = pack_bf(h2, h3);
    lv.x = pack_bf(l0, l1); lv.y = pack_bf(l2, l3);
    *reinterpret_cast<uint2*>(c_split + tiled_off(b, c4, 0)) = hv;
    *reinterpret_cast<uint2*>(c_split + tiled_off(b, c4, 1)) = lv;
}

// ---------------------------------------------------------------------------
// kernel_launch — single stream (R11 fork/join regressed; reverted)
// Inputs: 0=z_state 1=past_predictions 2=Wq 3=Wk 4=Wv 5=bq 6=bk 7=bv
// Output: context [512,1024] fp32
// ---------------------------------------------------------------------------
extern "C" void kernel_launch(void* const* d_in, const int* in_sizes, int n_in,
                              void* d_out, int out_size)
{
    const float* z    = (const float*)d_in[0];
    const float* past = (const float*)d_in[1];
    const float* Wq   = (const float*)d_in[2];
    const float* Wk   = (const float*)d_in[3];
    const float* Wv   = (const float*)d_in[4];
    const float* bq   = (const float*)d_in[5];
    // bk (d_in[6]) is softmax-invariant — unused.
    const float* bv   = (const float*)d_in[7];
    float* out = (float*)d_out;

    void *xa, *xb, *wq2, *wk2, *wv2, *up;
    cudaGetSymbolAddress(&xa, g_xa);
    cudaGetSymbolAddress(&xb, g_xb);
    cudaGetSymbolAddress(&wq2, g_wq2);
    cudaGetSymbolAddress(&wk2, g_wk2);
    cudaGetSymbolAddress(&wv2, g_wv2);
    cudaGetSymbolAddress(&up, g_u);
    char* xa_p  = (char*)xa;
    char* xb_p  = (char*)xb;
    char* wq2_p = (char*)wq2;
    char* wk2_p = (char*)wk2;
    char* wv2_p = (char*)wv2;
    float* u_buf = (float*)up;

    static int inited = 0;
    if (!inited) {
        cudaFuncSetAttribute(attn_kernel,
                             cudaFuncAttributeMaxDynamicSharedMemorySize, ATTN_SMEM);
        cudaFuncSetAttribute(mma_gemm<true, 1>,
                             cudaFuncAttributeMaxDynamicSharedMemorySize, SMEM_GEMM);
        cudaFuncSetAttribute(mma_gemm<false, 0>,
                             cudaFuncAttributeMaxDynamicSharedMemorySize, SMEM_GEMM);
        cudaFuncSetAttribute(mma_gemm<true, 0>,
                             cudaFuncAttributeMaxDynamicSharedMemorySize, SMEM_GEMM);
        inited = 1;
    }

    dim3 gg(FF / 64, BB / 64);   // (16, 8) = 128 CTAs

    // ONE prep launch: split z, Wq, Wv + transpose-split Wk (full chip)
    split_all<<<3584, 256>>>((const float4*)z, (const float4*)Wq,
                             (const float4*)Wv, Wk,
                             xa_p, wq2_p, wv2_p, wk2_p);
    // GEMM1: q = z @ Wq^T + bq -> tiled bf16 split into xb
    mma_gemm<true, 1><<<gg, 256, SMEM_GEMM>>>(xa_p, wq2_p, bq, xb_p);
    // GEMM2: u = q @ Wk (fp32)
    mma_gemm<false, 0><<<gg, 256, SMEM_GEMM>>>(xb_p, wk2_p, nullptr, u_buf);
    // attention: c[b] = softmax_t(u[b].p[b,t]) . p[b] -> tiled split into xa
    attn_kernel<<<BB, 256, ATTN_SMEM>>>(u_buf, past, xa_p);
    // GEMM3: out = c @ Wv^T + bv (fp32)
    mma_gemm<true, 0><<<gg, 256, SMEM_GEMM>>>(xa_p, wv2_p, bv, out);
}

// round 15
// speedup vs baseline: 1.1235x; 1.1235x over previous
#include <cuda_runtime.h>
#include <cuda_bf16.h>
#include <math.h>
#include <cstdint>

// Shapes (fixed per reference): B=512, T=256, F=D=1024
#define BB 512
#define TT 256
#define FF 1024

// ---------------- scratch (__device__ globals; no allocs allowed) -----------
// Split matrices stored TILED: block (rb, s) = rows [rb*64,+64) x k [s*64,+64)
//   -> 16 KB: [hi tile 8KB][lo tile 8KB], each tile 64 rows x 128B, XOR-swizzled.
__device__ __align__(16) __nv_bfloat16 g_xa[BB * 2048];   // split(z), then split(c)
__device__ __align__(16) __nv_bfloat16 g_xb[BB * 2048];   // split(q) (GEMM1 epi)
__device__ __align__(16) __nv_bfloat16 g_wq2[FF * 2048];  // split(Wq)
__device__ __align__(16) __nv_bfloat16 g_wk2[FF * 2048];  // splitT(Wk)
__device__ __align__(16) __nv_bfloat16 g_wv2[FF * 2048];  // split(Wv)
__device__ float g_u[BB * FF];

// ---------------- ptx helpers ----------------------------------------------
__device__ __forceinline__ uint32_t smem_u32(const void* p) {
    uint32_t a;
    asm("{ .reg .u64 t; cvta.to.shared.u64 t, %1; cvt.u32.u64 %0, t; }"
        : "=r"(a) : "l"(p));
    return a;
}
__device__ __forceinline__ void ldsm_x4(uint32_t (&r)[4], uint32_t addr) {
    asm volatile("ldmatrix.sync.aligned.m8n8.x4.shared.b16 {%0,%1,%2,%3}, [%4];"
                 : "=r"(r[0]), "=r"(r[1]), "=r"(r[2]), "=r"(r[3]) : "r"(addr));
}
__device__ __forceinline__ void mma_bf16(float (&d)[4], const uint32_t (&a)[4],
                                         uint32_t b0, uint32_t b1) {
    asm volatile(
        "mma.sync.aligned.m16n8k16.row.col.f32.bf16.bf16.f32 "
        "{%0,%1,%2,%3}, {%4,%5,%6,%7}, {%8,%9}, {%0,%1,%2,%3};"
        : "+f"(d[0]), "+f"(d[1]), "+f"(d[2]), "+f"(d[3])
        : "r"(a[0]), "r"(a[1]), "r"(a[2]), "r"(a[3]), "r"(b0), "r"(b1));
}

#define MBAR_INIT(a, c) asm volatile("mbarrier.init.shared.b64 [%0], %1;" :: "r"(a), "r"(c) : "memory")
#define MBAR_EXPECT(a, tx) asm volatile("mbarrier.arrive.expect_tx.shared.b64 _, [%0], %1;" :: "r"(a), "r"(tx) : "memory")
#define FENCE_ASYNC() asm volatile("fence.proxy.async.shared::cta;" ::: "memory")

__device__ __forceinline__ void bulk_g2s(uint32_t dst, const void* src,
                                         uint32_t bytes, uint32_t mbar) {
    asm volatile(
        "cp.async.bulk.shared::cluster.global.mbarrier::complete_tx::bytes "
        "[%0], [%1], %2, [%3];"
        :: "r"(dst), "l"(src), "r"(bytes), "r"(mbar) : "memory");
}

#define MBAR_WAIT(a, ph) do {                                                    \
    uint32_t _m = (a), _p = (ph), _d;                                            \
    asm volatile("{\n\t.reg .pred p;\n\t"                                        \
        "mbarrier.try_wait.parity.acquire.cta.shared::cta.b64 p, [%1], %2;\n\t"  \
        "selp.b32 %0, 1, 0, p;\n\t}" : "=r"(_d) : "r"(_m), "r"(_p) : "memory");  \
    if (!_d) {                                                                   \
        asm volatile("{\n\t.reg .pred P1;\n\t"                                   \
            "W%=:\n\t"                                                           \
            "mbarrier.try_wait.parity.acquire.cta.shared::cta.b64 P1, [%0], %1, 0x989680;\n\t" \
            "@P1 bra.uni D%=;\n\t"                                               \
            "bra.uni W%=;\n\t"                                                   \
            "D%=:\n\t}" :: "r"(_m), "r"(_p) : "memory");                         \
    }                                                                            \
} while (0)

// ---------------- fp32 -> bf16 hi/lo split + tiled addressing ----------------
__device__ __forceinline__ void split1(float x, __nv_bfloat16& h, __nv_bfloat16& l) {
    h = __float2bfloat16(x);
    l = __float2bfloat16(x - __bfloat162float(h));
}
__device__ __forceinline__ uint32_t pack_bf(__nv_bfloat16 a, __nv_bfloat16 b) {
    return (uint32_t)__bfloat16_as_ushort(a) | ((uint32_t)__bfloat16_as_ushort(b) << 16);
}
// byte offset of (row, kcol, part) in a tiled split array
__device__ __forceinline__ size_t tiled_off(int row, int kcol, int part) {
    int tb = (row >> 6) * 16 + (kcol >> 6);
    int r = row & 63, c = kcol & 63;
    return (size_t)tb * 16384 + (size_t)part * 8192
         + (size_t)(r * 128 + ((((c >> 3) ^ (r & 7))) << 4) + (c & 7) * 2);
}

// ---------------------------------------------------------------------------
// ONE merged prep kernel (single launch, full chip):
//   blocks [0,512)     : split(z)   -> g_xa
//   blocks [512,1536)  : split(Wq)  -> g_wq2
//   blocks [1536,2560) : split(Wv)  -> g_wv2
//   blocks [2560,3584) : splitT(Wk) -> g_wk2   (row=n, kcol=k)
// ---------------------------------------------------------------------------
__device__ __forceinline__ void split_rowmajor_block(
    const float4* __restrict__ in, char* __restrict__ out, int blk, int tid)
{
    int i = blk * 256 + tid;
    float4 v = in[i];
    int r = i >> 8, c4 = (i & 255) * 4;
    __nv_bfloat16 h0, h1, h2, h3, l0, l1, l2, l3;
    split1(v.x, h0, l0); split1(v.y, h1, l1);
    split1(v.z, h2, l2); split1(v.w, h3, l3);
    uint2 hv, lv;
    hv.x = pack_bf(h0, h1); hv.y = pack_bf(h2, h3);
    lv.x = pack_bf(l0, l1); lv.y = pack_bf(l2, l3);
    *reinterpret_cast<uint2*>(out + tiled_off(r, c4, 0)) = hv;
    *reinterpret_cast<uint2*>(out + tiled_off(r, c4, 1)) = lv;
}

__global__ __launch_bounds__(256)
void split_all(const float4* __restrict__ z, const float4* __restrict__ Wq,
               const float4* __restrict__ Wv, const float* __restrict__ Wk,
               char* __restrict__ xa, char* __restrict__ wq2,
               char* __restrict__ wv2, char* __restrict__ wk2)
{
    const int bid = blockIdx.x;
    const int tid = threadIdx.x;
    if (bid < 512) {
        split_rowmajor_block(z, xa, bid, tid);
    } else if (bid < 1536) {
        split_rowmajor_block(Wq, wq2, bid - 512, tid);
    } else if (bid < 2560) {
        split_rowmajor_block(Wv, wv2, bid - 1536, tid);
    } else {
        // transpose-split of Wk [K][N] -> tiled rows = n, kcols = k
        __shared__ float t[32][33];
        const int b2 = bid - 2560;
        const int k0 = (b2 & 31) * 32, n0 = (b2 >> 5) * 32;
        const int tx = tid & 31, ty = tid >> 5;   // ty 0..7
#pragma unroll
        for (int i = 0; i < 4; i++)
            t[ty * 4 + i][tx] = Wk[(size_t)(k0 + ty * 4 + i) * FF + n0 + tx];
        __syncthreads();
        // t[a][b] = Wk[k0+a][n0+b]; thread emits n = n0+tx, k = k0+ty*4..+3
        __nv_bfloat16 h[4], l[4];
#pragma unroll
        for (int i = 0; i < 4; i++) split1(t[ty * 4 + i][tx], h[i], l[i]);
        uint2 hv, lv;
        hv.x = pack_bf(h[0], h[1]); hv.y = pack_bf(h[2], h[3]);
        lv.x = pack_bf(l[0], l[1]); lv.y = pack_bf(l[2], l[3]);
        const int n = n0 + tx, kk = k0 + ty * 4;
        *reinterpret_cast<uint2*>(wk2 + tiled_off(n, kk, 0)) = hv;
        *reinterpret_cast<uint2*>(wk2 + tiled_off(n, kk, 1)) = lv;
    }
}

// ---------------------------------------------------------------------------
// HMMA bf16 NT GEMM on tiled split operands, bulk-copy pipeline.
//   D[512][1024] = (Ahi+Alo) @ (Bhi+Blo)^T  (3 passes, drops lo*lo).
// CTA tile 64x64, grid (16,8)=128 CTAs, 8 warps (2M x 4N), warp tile 32x16.
// 16 stages of BK=64; 3-slot smem ring, 32KB/slot ([Ahi|Alo|Bhi|Blo] 8KB each),
// filled by 2 cp.async.bulk per stage.
// OUTMODE 0: fp32 [512][1024] (+bias).  1: tiled split array (+bias).
// ---------------------------------------------------------------------------
#define STG_B 32768
#define SMEM_GEMM (1024 + 3 * STG_B)   // 99328

__device__ __forceinline__ void issue_stage(uint32_t mbar, uint32_t dst,
                                            const char* Atl, const char* Btl,
                                            int mb, int nb, int s)
{
    MBAR_EXPECT(mbar, 32768u);
    bulk_g2s(dst,          Atl + (size_t)(mb * 16 + s) * 16384, 16384u, mbar);
    bulk_g2s(dst + 16384u, Btl + (size_t)(nb * 16 + s) * 16384, 16384u, mbar);
}

template <bool HASBIAS, int OUTMODE>
__global__ __launch_bounds__(256)
void mma_gemm(const char* __restrict__ Atl, const char* __restrict__ Btl,
              const float* __restrict__ bias, void* __restrict__ Out)
{
    extern __shared__ char smem[];
    const uint32_t sb = smem_u32(smem);
    const int tid  = threadIdx.x;
    const int wid  = tid >> 5;
    const int lane = tid & 31;
    const int wm = wid >> 2;       // 2 M groups of 32 rows
    const int wn = wid & 3;        // 4 N groups of 16 cols
    const int nb = blockIdx.x;
    const int mb = blockIdx.y;

    const uint32_t tiles = sb + 1024;

    if (tid == 0) {
#pragma unroll
        for (int j = 0; j < 3; j++) MBAR_INIT(sb + 8 * j, 1);
        FENCE_ASYNC();
    }
    __syncthreads();
    if (tid == 0) {
#pragma unroll
        for (int p = 0; p < 3; p++)
            issue_stage(sb + 8 * p, tiles + p * STG_B, Atl, Btl, mb, nb, p);
    }

    // ldmatrix per-thread geometry
    const int q  = lane >> 3;
    const int lr = lane & 7;
    const int rowA0 = wm * 32 + (q & 1) * 8 + lr;        // mf adds 16
    const int rowB  = wn * 16 + (q >> 1) * 8 + lr;
    const uint32_t arow0 = rowA0 * 128, arow1 = (rowA0 + 16) * 128;
    const uint32_t brow  = rowB * 128;
    const int a0m = rowA0 & 7, a1m = (rowA0 + 16) & 7, bm = rowB & 7;
    const int qk = q >> 1, qb = q & 1;

    float acc[2][2][4];
#pragma unroll
    for (int i = 0; i < 2; i++)
#pragma unroll
        for (int j = 0; j < 2; j++)
#pragma unroll
            for (int e = 0; e < 4; e++) acc[i][j][e] = 0.f;

    for (int s = 0; s < 16; s++) {
        const int slot = s % 3;
        MBAR_WAIT(sb + 8 * slot, (s / 3) & 1);
        const uint32_t stg = tiles + slot * STG_B;

#pragma unroll
        for (int pass = 0; pass < 3; pass++) {
            const uint32_t ab = stg + ((pass == 1) ? 8192u : 0u);
            const uint32_t bb = stg + 16384u + ((pass == 2) ? 8192u : 0u);
#pragma unroll
            for (int kk = 0; kk < 4; kk++) {
                uint32_t a0[4], a1[4], b0[4];
                ldsm_x4(a0, ab + arow0 + (uint32_t)(((2 * kk + qk) ^ a0m) << 4));
                ldsm_x4(a1, ab + arow1 + (uint32_t)(((2 * kk + qk) ^ a1m) << 4));
                ldsm_x4(b0, bb + brow  + (uint32_t)(((2 * kk + qb) ^ bm)  << 4));
                mma_bf16(acc[0][0], a0, b0[0], b0[1]);
                mma_bf16(acc[0][1], a0, b0[2], b0[3]);
                mma_bf16(acc[1][0], a1, b0[0], b0[1]);
                mma_bf16(acc[1][1], a1, b0[2], b0[3]);
            }
        }
        __syncthreads();   // all warps done reading this slot
        if (tid == 0 && s + 3 < 16)
            issue_stage(sb + 8 * slot, stg, Atl, Btl, mb, nb, s + 3);
    }

    // epilogue
    const int r0 = mb * 64 + wm * 32 + (lane >> 2);
    const int cb = nb * 64 + wn * 16 + 2 * (lane & 3);
#pragma unroll
    for (int mf = 0; mf < 2; mf++) {
        const int rowA = r0 + mf * 16;
        const int rowB2 = rowA + 8;
#pragma unroll
        for (int nf = 0; nf < 2; nf++) {
            const int col = cb + nf * 8;
            float bx = 0.f, by = 0.f;
            if (HASBIAS) { bx = bias[col]; by = bias[col + 1]; }
            float d0 = acc[mf][nf][0] + bx, d1 = acc[mf][nf][1] + by;
            float d2 = acc[mf][nf][2] + bx, d3 = acc[mf][nf][3] + by;
            if (OUTMODE == 1) {
                char* o2 = (char*)Out;
                __nv_bfloat16 h0, h1, h2, h3, l0, l1, l2, l3;
                split1(d0, h0, l0); split1(d1, h1, l1);
                split1(d2, h2, l2); split1(d3, h3, l3);
                *reinterpret_cast<uint32_t*>(o2 + tiled_off(rowA, col, 0))  = pack_bf(h0, h1);
                *reinterpret_cast<uint32_t*>(o2 + tiled_off(rowA, col, 1))  = pack_bf(l0, l1);
                *reinterpret_cast<uint32_t*>(o2 + tiled_off(rowB2, col, 0)) = pack_bf(h2, h3);
                *reinterpret_cast<uint32_t*>(o2 + tiled_off(rowB2, col, 1)) = pack_bf(l2, l3);
            } else {
                float* o = (float*)Out;
                *reinterpret_cast<float2*>(o + (size_t)rowA * FF + col)  = make_float2(d0, d1);
                *reinterpret_cast<float2*>(o + (size_t)rowB2 * FF + col) = make_float2(d2, d3);
            }
        }
    }
}

// ---------------------------------------------------------------------------
// Fused single-query attention: one cp.async.bulk (32KB) per 8-row tile,
// 2-slot mbarrier ring (70.6KB smem -> 3 CTAs/SM), online softmax, single HBM
// pass over p. Epilogue writes c DIRECTLY as tiled bf16 split (GEMM3 A op).
// smem: [0,16) mbars | [64,96) s_sm | [1024,5120) u | [5120,+64K) tiles
// ---------------------------------------------------------------------------
#define ATTN_SMEM (5120 + 2 * 32768)   // 70656 -> 3 CTAs/SM

__global__ __launch_bounds__(256)
void attn_kernel(const float* __restrict__ u, const float* __restrict__ p,
                 char* __restrict__ c_split)
{
    extern __shared__ char smem[];
    const uint32_t sb = smem_u32(smem);
    float*  s_sm = (float*)(smem + 64);
    float4* u_s  = (float4*)(smem + 1024);

    const int b    = blockIdx.x;
    const int tid  = threadIdx.x;
    const int lane = tid & 31;
    const int w    = tid >> 5;

    if (tid == 0) {
        MBAR_INIT(sb + 0, 1);
        MBAR_INIT(sb + 8, 1);
        FENCE_ASYNC();
    }
    u_s[tid] = reinterpret_cast<const float4*>(u + (size_t)b * FF)[tid];
    __syncthreads();

    const char* pb = (const char*)(p + (size_t)b * TT * FF);
    if (tid == 0) {
        MBAR_EXPECT(sb + 0, 32768u);
        bulk_g2s(sb + 5120, pb, 32768u, sb + 0);
        MBAR_EXPECT(sb + 8, 32768u);
        bulk_g2s(sb + 5120 + 32768, pb + 32768, 32768u, sb + 8);
    }

    float4 acc = make_float4(0.f, 0.f, 0.f, 0.f);
    float m = -INFINITY;
    float l = 0.f;

    for (int it = 0; it < TT / 8; it++) {
        const int slot = it & 1;
        MBAR_WAIT(sb + 8 * slot, (it >> 1) & 1);
        const float4* tile = (const float4*)(smem + 5120 + slot * 32768);

        // scores: warp w computes dot(u, local row w)
        float partial = 0.f;
#pragma unroll
        for (int k = 0; k < 8; k++) {
            float4 a  = tile[w * 256 + k * 32 + lane];
            float4 uu = u_s[k * 32 + lane];
            partial += a.x * uu.x + a.y * uu.y + a.z * uu.z + a.w * uu.w;
        }
#pragma unroll
        for (int off = 16; off; off >>= 1)
            partial += __shfl_xor_sync(0xffffffffu, partial, off);
        if (lane == 0) s_sm[w] = partial;
        __syncthreads();

        // online softmax (redundant per thread, identical values)
        float s0[8], wv[8];
        float tmax = -INFINITY;
#pragma unroll
        for (int i = 0; i < 8; i++) { s0[i] = s_sm[i]; tmax = fmaxf(tmax, s0[i]); }
        float m_new = fmaxf(m, tmax);
        float cf = __expf(m - m_new);   // it=0: exp(-inf)=0, acc is 0 anyway
        float wsum = 0.f;
#pragma unroll
        for (int i = 0; i < 8; i++) { wv[i] = __expf(s0[i] - m_new); wsum += wv[i]; }
        l = l * cf + wsum;
        m = m_new;
        acc.x *= cf; acc.y *= cf; acc.z *= cf; acc.w *= cf;

#pragma unroll
        for (int i = 0; i < 8; i++) {
            float4 v = tile[i * 256 + tid];
            acc.x += wv[i] * v.x;
            acc.y += wv[i] * v.y;
            acc.z += wv[i] * v.z;
            acc.w += wv[i] * v.w;
        }
        __syncthreads();   // everyone done with this slot (and s_sm)

        if (tid == 0 && it + 2 < TT / 8) {
            MBAR_EXPECT(sb + 8 * slot, 32768u);
            bulk_g2s(sb + 5120 + slot * 32768, pb + (size_t)(it + 2) * 32768,
                     32768u, sb + 8 * slot);
        }
    }

    // epilogue: c[b][tid*4..+3] -> tiled bf16 split (GEMM3 A operand)
    const float inv = 1.f / l;
    const int c4 = tid * 4;
    __nv_bfloat16 h0, h1, h2, h3, l0, l1, l2, l3;
    split1(acc.x * inv, h0, l0); split1(acc.y * inv, h1, l1);
    split1(acc.z * inv, h2, l2); split1(acc.w * inv, h3, l3);
    uint2 hv, lv;
    hv.x = pack_bf(h0, h1); hv.y = pack_bf(h2, h3);
    lv.x = pack_bf(l0, l1); lv.y = pack_bf(l2, l3);
    *reinterpret_cast<uint2*>(c_split + tiled_off(b, c4, 0)) = hv;
    *reinterpret_cast<uint2*>(c_split + tiled_off(b, c4, 1)) = lv;
}

// ---------------------------------------------------------------------------
// kernel_launch — single stream
// Inputs: 0=z_state 1=past_predictions 2=Wq 3=Wk 4=Wv 5=bq 6=bk 7=bv
// Output: context [512,1024] fp32
// ---------------------------------------------------------------------------
extern "C" void kernel_launch(void* const* d_in, const int* in_sizes, int n_in,
                              void* d_out, int out_size)
{
    const float* z    = (const float*)d_in[0];
    const float* past = (const float*)d_in[1];
    const float* Wq   = (const float*)d_in[2];
    const float* Wk   = (const float*)d_in[3];
    const float* Wv   = (const float*)d_in[4];
    const float* bq   = (const float*)d_in[5];
    // bk (d_in[6]) is softmax-invariant — unused.
    const float* bv   = (const float*)d_in[7];
    float* out = (float*)d_out;

    void *xa, *xb, *wq2, *wk2, *wv2, *up;
    cudaGetSymbolAddress(&xa, g_xa);
    cudaGetSymbolAddress(&xb, g_xb);
    cudaGetSymbolAddress(&wq2, g_wq2);
    cudaGetSymbolAddress(&wk2, g_wk2);
    cudaGetSymbolAddress(&wv2, g_wv2);
    cudaGetSymbolAddress(&up, g_u);
    char* xa_p  = (char*)xa;
    char* xb_p  = (char*)xb;
    char* wq2_p = (char*)wq2;
    char* wk2_p = (char*)wk2;
    char* wv2_p = (char*)wv2;
    float* u_buf = (float*)up;

    static int inited = 0;
    if (!inited) {
        cudaFuncSetAttribute(attn_kernel,
                             cudaFuncAttributeMaxDynamicSharedMemorySize, ATTN_SMEM);
        cudaFuncSetAttribute(mma_gemm<true, 1>,
                             cudaFuncAttributeMaxDynamicSharedMemorySize, SMEM_GEMM);
        cudaFuncSetAttribute(mma_gemm<false, 0>,
                             cudaFuncAttributeMaxDynamicSharedMemorySize, SMEM_GEMM);
        cudaFuncSetAttribute(mma_gemm<true, 0>,
                             cudaFuncAttributeMaxDynamicSharedMemorySize, SMEM_GEMM);
        inited = 1;
    }

    dim3 gg(FF / 64, BB / 64);   // (16, 8) = 128 CTAs

    // ONE prep launch: split z, Wq, Wv + transpose-split Wk (full chip)
    split_all<<<3584, 256>>>((const float4*)z, (const float4*)Wq,
                             (const float4*)Wv, Wk,
                             xa_p, wq2_p, wv2_p, wk2_p);
    // GEMM1: q = z @ Wq^T + bq -> tiled bf16 split into xb
    mma_gemm<true, 1><<<gg, 256, SMEM_GEMM>>>(xa_p, wq2_p, bq, xb_p);
    // GEMM2: u = q @ Wk (fp32)
    mma_gemm<false, 0><<<gg, 256, SMEM_GEMM>>>(xb_p, wk2_p, nullptr, u_buf);
    // attention: c[b] = softmax_t(u[b].p[b,t]) . p[b] -> tiled split into xa
    attn_kernel<<<BB, 256, ATTN_SMEM>>>(u_buf, past, xa_p);
    // GEMM3: out = c @ Wv^T + bv (fp32)
    mma_gemm<true, 0><<<gg, 256, SMEM_GEMM>>>(xa_p, wv2_p, bv, out);
}

// round 16
// speedup vs baseline: 1.3619x; 1.2122x over previous
#include <cuda_runtime.h>
#include <cuda_bf16.h>
#include <math.h>
#include <cstdint>

// Shapes (fixed per reference): B=512, T=256, F=D=1024
#define BB 512
#define TT 256
#define FF 1024

// ---------------- scratch (__device__ globals; no allocs allowed) -----------
// Split matrices stored TILED: block (rb, s) = rows [rb*64,+64) x k [s*64,+64)
//   -> 16 KB: [hi tile 8KB][lo tile 8KB], each tile 64 rows x 128B, XOR-swizzled.
__device__ __align__(16) __nv_bfloat16 g_xa[BB * 2048];   // split(z), then split(c)
__device__ __align__(16) __nv_bfloat16 g_xb[BB * 2048];   // split(q) (GEMM1 epi)
__device__ __align__(16) __nv_bfloat16 g_wq2[FF * 2048];  // split(Wq)
__device__ __align__(16) __nv_bfloat16 g_wk2[FF * 2048];  // splitT(Wk)
__device__ __align__(16) __nv_bfloat16 g_wv2[FF * 2048];  // split(Wv)
__device__ float g_u[BB * FF];

// ---------------- ptx helpers ----------------------------------------------
__device__ __forceinline__ uint32_t smem_u32(const void* p) {
    uint32_t a;
    asm("{ .reg .u64 t; cvta.to.shared.u64 t, %1; cvt.u32.u64 %0, t; }"
        : "=r"(a) : "l"(p));
    return a;
}
__device__ __forceinline__ void ldsm_x4(uint32_t (&r)[4], uint32_t addr) {
    asm volatile("ldmatrix.sync.aligned.m8n8.x4.shared.b16 {%0,%1,%2,%3}, [%4];"
                 : "=r"(r[0]), "=r"(r[1]), "=r"(r[2]), "=r"(r[3]) : "r"(addr));
}
__device__ __forceinline__ void mma_bf16(float (&d)[4], const uint32_t (&a)[4],
                                         uint32_t b0, uint32_t b1) {
    asm volatile(
        "mma.sync.aligned.m16n8k16.row.col.f32.bf16.bf16.f32 "
        "{%0,%1,%2,%3}, {%4,%5,%6,%7}, {%8,%9}, {%0,%1,%2,%3};"
        : "+f"(d[0]), "+f"(d[1]), "+f"(d[2]), "+f"(d[3])
        : "r"(a[0]), "r"(a[1]), "r"(a[2]), "r"(a[3]), "r"(b0), "r"(b1));
}

#define MBAR_INIT(a, c) asm volatile("mbarrier.init.shared.b64 [%0], %1;" :: "r"(a), "r"(c) : "memory")
#define MBAR_EXPECT(a, tx) asm volatile("mbarrier.arrive.expect_tx.shared.b64 _, [%0], %1;" :: "r"(a), "r"(tx) : "memory")
#define FENCE_ASYNC() asm volatile("fence.proxy.async.shared::cta;" ::: "memory")

__device__ __forceinline__ void bulk_g2s(uint32_t dst, const void* src,
                                         uint32_t bytes, uint32_t mbar) {
    asm volatile(
        "cp.async.bulk.shared::cluster.global.mbarrier::complete_tx::bytes "
        "[%0], [%1], %2, [%3];"
        :: "r"(dst), "l"(src), "r"(bytes), "r"(mbar) : "memory");
}

#define MBAR_WAIT(a, ph) do {                                                    \
    uint32_t _m = (a), _p = (ph), _d;                                            \
    asm volatile("{\n\t.reg .pred p;\n\t"                                        \
        "mbarrier.try_wait.parity.acquire.cta.shared::cta.b64 p, [%1], %2;\n\t"  \
        "selp.b32 %0, 1, 0, p;\n\t}" : "=r"(_d) : "r"(_m), "r"(_p) : "memory");  \
    if (!_d) {                                                                   \
        asm volatile("{\n\t.reg .pred P1;\n\t"                                   \
            "W%=:\n\t"                                                           \
            "mbarrier.try_wait.parity.acquire.cta.shared::cta.b64 P1, [%0], %1, 0x989680;\n\t" \
            "@P1 bra.uni D%=;\n\t"                                               \
            "bra.uni W%=;\n\t"                                                   \
            "D%=:\n\t}" :: "r"(_m), "r"(_p) : "memory");                         \
    }                                                                            \
} while (0)

// ---------------- fp32 -> bf16 hi/lo split + tiled addressing ----------------
__device__ __forceinline__ void split1(float x, __nv_bfloat16& h, __nv_bfloat16& l) {
    h = __float2bfloat16(x);
    l = __float2bfloat16(x - __bfloat162float(h));
}
__device__ __forceinline__ uint32_t pack_bf(__nv_bfloat16 a, __nv_bfloat16 b) {
    return (uint32_t)__bfloat16_as_ushort(a) | ((uint32_t)__bfloat16_as_ushort(b) << 16);
}
// byte offset of (row, kcol, part) in a tiled split array
__device__ __forceinline__ size_t tiled_off(int row, int kcol, int part) {
    int tb = (row >> 6) * 16 + (kcol >> 6);
    int r = row & 63, c = kcol & 63;
    return (size_t)tb * 16384 + (size_t)part * 8192
         + (size_t)(r * 128 + ((((c >> 3) ^ (r & 7))) << 4) + (c & 7) * 2);
}

// ---------------------------------------------------------------------------
// ONE merged prep kernel (single launch, full chip):
//   blocks [0,512)     : split(z)   -> g_xa
//   blocks [512,1536)  : split(Wq)  -> g_wq2
//   blocks [1536,2560) : split(Wv)  -> g_wv2
//   blocks [2560,3584) : splitT(Wk) -> g_wk2   (row=n, kcol=k)
// ---------------------------------------------------------------------------
__device__ __forceinline__ void split_rowmajor_block(
    const float4* __restrict__ in, char* __restrict__ out, int blk, int tid)
{
    int i = blk * 256 + tid;
    float4 v = in[i];
    int r = i >> 8, c4 = (i & 255) * 4;
    __nv_bfloat16 h0, h1, h2, h3, l0, l1, l2, l3;
    split1(v.x, h0, l0); split1(v.y, h1, l1);
    split1(v.z, h2, l2); split1(v.w, h3, l3);
    uint2 hv, lv;
    hv.x = pack_bf(h0, h1); hv.y = pack_bf(h2, h3);
    lv.x = pack_bf(l0, l1); lv.y = pack_bf(l2, l3);
    *reinterpret_cast<uint2*>(out + tiled_off(r, c4, 0)) = hv;
    *reinterpret_cast<uint2*>(out + tiled_off(r, c4, 1)) = lv;
}

__global__ __launch_bounds__(256)
void split_all(const float4* __restrict__ z, const float4* __restrict__ Wq,
               const float4* __restrict__ Wv, const float* __restrict__ Wk,
               char* __restrict__ xa, char* __restrict__ wq2,
               char* __restrict__ wv2, char* __restrict__ wk2)
{
    const int bid = blockIdx.x;
    const int tid = threadIdx.x;
    if (bid < 512) {
        split_rowmajor_block(z, xa, bid, tid);
    } else if (bid < 1536) {
        split_rowmajor_block(Wq, wq2, bid - 512, tid);
    } else if (bid < 2560) {
        split_rowmajor_block(Wv, wv2, bid - 1536, tid);
    } else {
        // transpose-split of Wk [K][N] -> tiled rows = n, kcols = k
        __shared__ float t[32][33];
        const int b2 = bid - 2560;
        const int k0 = (b2 & 31) * 32, n0 = (b2 >> 5) * 32;
        const int tx = tid & 31, ty = tid >> 5;   // ty 0..7
#pragma unroll
        for (int i = 0; i < 4; i++)
            t[ty * 4 + i][tx] = Wk[(size_t)(k0 + ty * 4 + i) * FF + n0 + tx];
        __syncthreads();
        // t[a][b] = Wk[k0+a][n0+b]; thread emits n = n0+tx, k = k0+ty*4..+3
        __nv_bfloat16 h[4], l[4];
#pragma unroll
        for (int i = 0; i < 4; i++) split1(t[ty * 4 + i][tx], h[i], l[i]);
        uint2 hv, lv;
        hv.x = pack_bf(h[0], h[1]); hv.y = pack_bf(h[2], h[3]);
        lv.x = pack_bf(l[0], l[1]); lv.y = pack_bf(l[2], l[3]);
        const int n = n0 + tx, kk = k0 + ty * 4;
        *reinterpret_cast<uint2*>(wk2 + tiled_off(n, kk, 0)) = hv;
        *reinterpret_cast<uint2*>(wk2 + tiled_off(n, kk, 1)) = lv;
    }
}

// ---------------------------------------------------------------------------
// HMMA bf16 NT GEMM on tiled split operands, bulk-copy pipeline.
//   D[512][1024] = (Ahi+Alo) @ (Bhi+Blo)^T  (3 passes, drops lo*lo).
// CTA tile 64x64, grid (16,8)=128 CTAs, 8 warps (2M x 4N), warp tile 32x16.
// 16 stages of BK=64; 3-slot smem ring, 32KB/slot ([Ahi|Alo|Bhi|Blo] 8KB each),
// filled by 2 cp.async.bulk per stage.
// OUTMODE 0: fp32 [512][1024] (+bias).  1: tiled split array (+bias).
// ---------------------------------------------------------------------------
#define STG_B 32768
#define SMEM_GEMM (1024 + 3 * STG_B)   // 99328

__device__ __forceinline__ void issue_stage(uint32_t mbar, uint32_t dst,
                                            const char* Atl, const char* Btl,
                                            int mb, int nb, int s)
{
    MBAR_EXPECT(mbar, 32768u);
    bulk_g2s(dst,          Atl + (size_t)(mb * 16 + s) * 16384, 16384u, mbar);
    bulk_g2s(dst + 16384u, Btl + (size_t)(nb * 16 + s) * 16384, 16384u, mbar);
}

template <bool HASBIAS, int OUTMODE>
__global__ __launch_bounds__(256)
void mma_gemm(const char* __restrict__ Atl, const char* __restrict__ Btl,
              const float* __restrict__ bias, void* __restrict__ Out)
{
    extern __shared__ char smem[];
    const uint32_t sb = smem_u32(smem);
    const int tid  = threadIdx.x;
    const int wid  = tid >> 5;
    const int lane = tid & 31;
    const int wm = wid >> 2;       // 2 M groups of 32 rows
    const int wn = wid & 3;        // 4 N groups of 16 cols
    const int nb = blockIdx.x;
    const int mb = blockIdx.y;

    const uint32_t tiles = sb + 1024;

    if (tid == 0) {
#pragma unroll
        for (int j = 0; j < 3; j++) MBAR_INIT(sb + 8 * j, 1);
        FENCE_ASYNC();
    }
    __syncthreads();
    if (tid == 0) {
#pragma unroll
        for (int p = 0; p < 3; p++)
            issue_stage(sb + 8 * p, tiles + p * STG_B, Atl, Btl, mb, nb, p);
    }

    // ldmatrix per-thread geometry
    const int q  = lane >> 3;
    const int lr = lane & 7;
    const int rowA0 = wm * 32 + (q & 1) * 8 + lr;        // mf adds 16
    const int rowB  = wn * 16 + (q >> 1) * 8 + lr;
    const uint32_t arow0 = rowA0 * 128, arow1 = (rowA0 + 16) * 128;
    const uint32_t brow  = rowB * 128;
    const int a0m = rowA0 & 7, a1m = (rowA0 + 16) & 7, bm = rowB & 7;
    const int qk = q >> 1, qb = q & 1;

    float acc[2][2][4];
#pragma unroll
    for (int i = 0; i < 2; i++)
#pragma unroll
        for (int j = 0; j < 2; j++)
#pragma unroll
            for (int e = 0; e < 4; e++) acc[i][j][e] = 0.f;

    for (int s = 0; s < 16; s++) {
        const int slot = s % 3;
        MBAR_WAIT(sb + 8 * slot, (s / 3) & 1);
        const uint32_t stg = tiles + slot * STG_B;

#pragma unroll
        for (int pass = 0; pass < 3; pass++) {
            const uint32_t ab = stg + ((pass == 1) ? 8192u : 0u);
            const uint32_t bb = stg + 16384u + ((pass == 2) ? 8192u : 0u);
#pragma unroll
            for (int kk = 0; kk < 4; kk++) {
                uint32_t a0[4], a1[4], b0[4];
                ldsm_x4(a0, ab + arow0 + (uint32_t)(((2 * kk + qk) ^ a0m) << 4));
                ldsm_x4(a1, ab + arow1 + (uint32_t)(((2 * kk + qk) ^ a1m) << 4));
                ldsm_x4(b0, bb + brow  + (uint32_t)(((2 * kk + qb) ^ bm)  << 4));
                mma_bf16(acc[0][0], a0, b0[0], b0[1]);
                mma_bf16(acc[0][1], a0, b0[2], b0[3]);
                mma_bf16(acc[1][0], a1, b0[0], b0[1]);
                mma_bf16(acc[1][1], a1, b0[2], b0[3]);
            }
        }
        __syncthreads();   // all warps done reading this slot
        if (tid == 0 && s + 3 < 16)
            issue_stage(sb + 8 * slot, stg, Atl, Btl, mb, nb, s + 3);
    }

    // epilogue
    const int r0 = mb * 64 + wm * 32 + (lane >> 2);
    const int cb = nb * 64 + wn * 16 + 2 * (lane & 3);
#pragma unroll
    for (int mf = 0; mf < 2; mf++) {
        const int rowA = r0 + mf * 16;
        const int rowB2 = rowA + 8;
#pragma unroll
        for (int nf = 0; nf < 2; nf++) {
            const int col = cb + nf * 8;
            float bx = 0.f, by = 0.f;
            if (HASBIAS) { bx = bias[col]; by = bias[col + 1]; }
            float d0 = acc[mf][nf][0] + bx, d1 = acc[mf][nf][1] + by;
            float d2 = acc[mf][nf][2] + bx, d3 = acc[mf][nf][3] + by;
            if (OUTMODE == 1) {
                char* o2 = (char*)Out;
                __nv_bfloat16 h0, h1, h2, h3, l0, l1, l2, l3;
                split1(d0, h0, l0); split1(d1, h1, l1);
                split1(d2, h2, l2); split1(d3, h3, l3);
                *reinterpret_cast<uint32_t*>(o2 + tiled_off(rowA, col, 0))  = pack_bf(h0, h1);
                *reinterpret_cast<uint32_t*>(o2 + tiled_off(rowA, col, 1))  = pack_bf(l0, l1);
                *reinterpret_cast<uint32_t*>(o2 + tiled_off(rowB2, col, 0)) = pack_bf(h2, h3);
                *reinterpret_cast<uint32_t*>(o2 + tiled_off(rowB2, col, 1)) = pack_bf(l2, l3);
            } else {
                float* o = (float*)Out;
                *reinterpret_cast<float2*>(o + (size_t)rowA * FF + col)  = make_float2(d0, d1);
                *reinterpret_cast<float2*>(o + (size_t)rowB2 * FF + col) = make_float2(d2, d3);
            }
        }
    }
}

// ---------------------------------------------------------------------------
// Fused single-query attention, SINGLE-WAVE config:
//   4-row tiles (16KB/slot), 2-slot bulk ring, smem 37.9KB + launch_bounds
//   (256,5) -> 5 CTAs/SM -> 740 slots >= 512 CTAs: no second wave.
// Scores: warp w computes row (w&3) over feature-half (w>>3? no: w>>2);
//   halves combined via s_sm[r] + s_sm[r+4] after the barrier.
// Epilogue writes c DIRECTLY as tiled bf16 split (GEMM3 A operand).
// smem: [0,16) mbars | [64,96) s_sm | [1024,5120) u | [5120,+32K) tiles
// ---------------------------------------------------------------------------
#define ATTN_SLOT 16384
#define ATTN_SMEM (5120 + 2 * ATTN_SLOT)   // 37888 -> 5 CTAs/SM (reg-capped)
#define NIT (TT / 4)                        // 64 iterations

__global__ __launch_bounds__(256, 5)
void attn_kernel(const float* __restrict__ u, const float* __restrict__ p,
                 char* __restrict__ c_split)
{
    extern __shared__ char smem[];
    const uint32_t sb = smem_u32(smem);
    float*  s_sm = (float*)(smem + 64);
    float4* u_s  = (float4*)(smem + 1024);

    const int b    = blockIdx.x;
    const int tid  = threadIdx.x;
    const int lane = tid & 31;
    const int w    = tid >> 5;
    const int wr   = w & 3;        // row within 4-row tile
    const int wh   = w >> 2;       // feature half (0/1)

    if (tid == 0) {
        MBAR_INIT(sb + 0, 1);
        MBAR_INIT(sb + 8, 1);
        FENCE_ASYNC();
    }
    u_s[tid] = reinterpret_cast<const float4*>(u + (size_t)b * FF)[tid];
    __syncthreads();

    const char* pb = (const char*)(p + (size_t)b * TT * FF);
    if (tid == 0) {
        MBAR_EXPECT(sb + 0, (uint32_t)ATTN_SLOT);
        bulk_g2s(sb + 5120, pb, (uint32_t)ATTN_SLOT, sb + 0);
        MBAR_EXPECT(sb + 8, (uint32_t)ATTN_SLOT);
        bulk_g2s(sb + 5120 + ATTN_SLOT, pb + ATTN_SLOT, (uint32_t)ATTN_SLOT, sb + 8);
    }

    float4 acc = make_float4(0.f, 0.f, 0.f, 0.f);
    float m = -INFINITY;
    float l = 0.f;

    for (int it = 0; it < NIT; it++) {
        const int slot = it & 1;
        MBAR_WAIT(sb + 8 * slot, (it >> 1) & 1);
        const float4* tile = (const float4*)(smem + 5120 + slot * ATTN_SLOT);

        // scores: warp w -> row wr, feature half wh (512 features)
        float partial = 0.f;
#pragma unroll
        for (int k = 0; k < 4; k++) {
            float4 a  = tile[wr * 256 + wh * 128 + k * 32 + lane];
            float4 uu = u_s[wh * 128 + k * 32 + lane];
            partial += a.x * uu.x + a.y * uu.y + a.z * uu.z + a.w * uu.w;
        }
#pragma unroll
        for (int off = 16; off; off >>= 1)
            partial += __shfl_xor_sync(0xffffffffu, partial, off);
        if (lane == 0) s_sm[w] = partial;
        __syncthreads();

        // online softmax over 4 rows (redundant per thread, identical values)
        float s0[4], wv[4];
        float tmax = -INFINITY;
#pragma unroll
        for (int i = 0; i < 4; i++) {
            s0[i] = s_sm[i] + s_sm[i + 4];
            tmax = fmaxf(tmax, s0[i]);
        }
        float m_new = fmaxf(m, tmax);
        float cf = __expf(m - m_new);   // it=0: exp(-inf)=0, acc is 0 anyway
        float wsum = 0.f;
#pragma unroll
        for (int i = 0; i < 4; i++) { wv[i] = __expf(s0[i] - m_new); wsum += wv[i]; }
        l = l * cf + wsum;
        m = m_new;
        acc.x *= cf; acc.y *= cf; acc.z *= cf; acc.w *= cf;

#pragma unroll
        for (int i = 0; i < 4; i++) {
            float4 v = tile[i * 256 + tid];
            acc.x += wv[i] * v.x;
            acc.y += wv[i] * v.y;
            acc.z += wv[i] * v.z;
            acc.w += wv[i] * v.w;
        }
        __syncthreads();   // everyone done with this slot (and s_sm)

        if (tid == 0 && it + 2 < NIT) {
            MBAR_EXPECT(sb + 8 * slot, (uint32_t)ATTN_SLOT);
            bulk_g2s(sb + 5120 + slot * ATTN_SLOT,
                     pb + (size_t)(it + 2) * ATTN_SLOT,
                     (uint32_t)ATTN_SLOT, sb + 8 * slot);
        }
    }

    // epilogue: c[b][tid*4..+3] -> tiled bf16 split (GEMM3 A operand)
    const float inv = 1.f / l;
    const int c4 = tid * 4;
    __nv_bfloat16 h0, h1, h2, h3, l0, l1, l2, l3;
    split1(acc.x * inv, h0, l0); split1(acc.y * inv, h1, l1);
    split1(acc.z * inv, h2, l2); split1(acc.w * inv, h3, l3);
    uint2 hv, lv;
    hv.x = pack_bf(h0, h1); hv.y = pack_bf(h2, h3);
    lv.x = pack_bf(l0, l1); lv.y = pack_bf(l2, l3);
    *reinterpret_cast<uint2*>(c_split + tiled_off(b, c4, 0)) = hv;
    *reinterpret_cast<uint2*>(c_split + tiled_off(b, c4, 1)) = lv;
}

// ---------------------------------------------------------------------------
// kernel_launch — single stream
// Inputs: 0=z_state 1=past_predictions 2=Wq 3=Wk 4=Wv 5=bq 6=bk 7=bv
// Output: context [512,1024] fp32
// ---------------------------------------------------------------------------
extern "C" void kernel_launch(void* const* d_in, const int* in_sizes, int n_in,
                              void* d_out, int out_size)
{
    const float* z    = (const float*)d_in[0];
    const float* past = (const float*)d_in[1];
    const float* Wq   = (const float*)d_in[2];
    const float* Wk   = (const float*)d_in[3];
    const float* Wv   = (const float*)d_in[4];
    const float* bq   = (const float*)d_in[5];
    // bk (d_in[6]) is softmax-invariant — unused.
    const float* bv   = (const float*)d_in[7];
    float* out = (float*)d_out;

    void *xa, *xb, *wq2, *wk2, *wv2, *up;
    cudaGetSymbolAddress(&xa, g_xa);
    cudaGetSymbolAddress(&xb, g_xb);
    cudaGetSymbolAddress(&wq2, g_wq2);
    cudaGetSymbolAddress(&wk2, g_wk2);
    cudaGetSymbolAddress(&wv2, g_wv2);
    cudaGetSymbolAddress(&up, g_u);
    char* xa_p  = (char*)xa;
    char* xb_p  = (char*)xb;
    char* wq2_p = (char*)wq2;
    char* wk2_p = (char*)wk2;
    char* wv2_p = (char*)wv2;
    float* u_buf = (float*)up;

    static int inited = 0;
    if (!inited) {
        cudaFuncSetAttribute(attn_kernel,
                             cudaFuncAttributeMaxDynamicSharedMemorySize, ATTN_SMEM);
        cudaFuncSetAttribute(mma_gemm<true, 1>,
                             cudaFuncAttributeMaxDynamicSharedMemorySize, SMEM_GEMM);
        cudaFuncSetAttribute(mma_gemm<false, 0>,
                             cudaFuncAttributeMaxDynamicSharedMemorySize, SMEM_GEMM);
        cudaFuncSetAttribute(mma_gemm<true, 0>,
                             cudaFuncAttributeMaxDynamicSharedMemorySize, SMEM_GEMM);
        inited = 1;
    }

    dim3 gg(FF / 64, BB / 64);   // (16, 8) = 128 CTAs

    // ONE prep launch: split z, Wq, Wv + transpose-split Wk (full chip)
    split_all<<<3584, 256>>>((const float4*)z, (const float4*)Wq,
                             (const float4*)Wv, Wk,
                             xa_p, wq2_p, wv2_p, wk2_p);
    // GEMM1: q = z @ Wq^T + bq -> tiled bf16 split into xb
    mma_gemm<true, 1><<<gg, 256, SMEM_GEMM>>>(xa_p, wq2_p, bq, xb_p);
    // GEMM2: u = q @ Wk (fp32)
    mma_gemm<false, 0><<<gg, 256, SMEM_GEMM>>>(xb_p, wk2_p, nullptr, u_buf);
    // attention: c[b] = softmax_t(u[b].p[b,t]) . p[b] -> tiled split into xa
    attn_kernel<<<BB, 256, ATTN_SMEM>>>(u_buf, past, xa_p);
    // GEMM3: out = c @ Wv^T + bv (fp32)
    mma_gemm<true, 0><<<gg, 256, SMEM_GEMM>>>(xa_p, wv2_p, bv, out);
}